// round 9
// baseline (speedup 1.0000x reference)
#include <cuda_runtime.h>
#include <cuda_bf16.h>
#include <cstdio>

#define D 128
#define ESZ 20
#define MAX_NODES 20000
#define MAX_EDGES 600000
#define CUTOFF 5.0f

// ---------------- scratch (static device bss; no allocations) ----------------
__device__ __align__(16) float g_h1 [MAX_NODES * D];
__device__ __align__(16) float g_so [MAX_NODES * 3 * D];
__device__ __align__(16) float g_s  [MAX_NODES * D];
__device__ __align__(16) float g_v  [MAX_NODES * 3 * D];
__device__ __align__(16) float g_Uv [MAX_NODES * 3 * D];
__device__ __align__(16) float g_Vv [MAX_NODES * 3 * D];
__device__ __align__(16) float g_cat[MAX_NODES * 2 * D];
__device__ __align__(16) float g_ip [MAX_NODES * D];
__device__ __align__(16) float g_h2 [MAX_NODES * D];
__device__ __align__(16) float g_a  [MAX_NODES * 3 * D];
// CSR scratch
__device__ int g_cnt [MAX_NODES];
__device__ int g_cur [MAX_NODES];
__device__ int g_off [MAX_NODES + 1];
__device__ int g_perm[MAX_EDGES];

// ---------------- helpers ----------------
__device__ __forceinline__ void red_add_v2(float* addr, float2 v) {
    asm volatile("red.global.add.v2.f32 [%0], {%1, %2};"
                 :: "l"(addr), "f"(v.x), "f"(v.y) : "memory");
}
__device__ __forceinline__ float silu_f(float x) {
    return x / (1.0f + __expf(-x));
}

// ---------------- CSR build ----------------
__global__ void csr_zero_kernel(int n) {
    int i = blockIdx.x * blockDim.x + threadIdx.x;
    if (i < n) { g_cnt[i] = 0; g_cur[i] = 0; }
}
__global__ void csr_hist_kernel(const int* __restrict__ eidx, int E) {
    int e = blockIdx.x * blockDim.x + threadIdx.x;
    if (e < E) atomicAdd(&g_cnt[eidx[2 * e + 1]], 1);
}
__global__ void csr_scan_kernel(int n) {
    __shared__ int sm[1024];
    int t = threadIdx.x;
    int per = (n + 1023) / 1024;
    int base = t * per;
    int sum = 0;
    for (int i = 0; i < per; i++) {
        int b = base + i;
        if (b < n) sum += g_cnt[b];
    }
    sm[t] = sum;
    __syncthreads();
    for (int off = 1; off < 1024; off <<= 1) {
        int v = 0;
        if (t >= off) v = sm[t - off];
        __syncthreads();
        if (t >= off) sm[t] += v;
        __syncthreads();
    }
    int run = (t == 0) ? 0 : sm[t - 1];
    for (int i = 0; i < per; i++) {
        int b = base + i;
        if (b < n) { g_off[b] = run; run += g_cnt[b]; }
    }
    if (t == 1023) g_off[n] = sm[1023];
}
__global__ void csr_scatter_kernel(const int* __restrict__ eidx, int E) {
    int e = blockIdx.x * blockDim.x + threadIdx.x;
    if (e < E) {
        int dst = eidx[2 * e + 1];
        int pos = g_off[dst] + atomicAdd(&g_cur[dst], 1);
        g_perm[pos] = e;
    }
}

// ---------------- init: copy node states into accumulators ----------------
__global__ void init_copy_kernel(const float* __restrict__ ns, const float* __restrict__ nv, int n) {
    int tid = blockIdx.x * blockDim.x + threadIdx.x;
    int stride = gridDim.x * blockDim.x;
    const float4* ns4 = (const float4*)ns;
    const float4* nv4 = (const float4*)nv;
    float4* s4 = (float4*)g_s;
    float4* v4 = (float4*)g_v;
    int cs = n * (D / 4);
    int cv = n * (3 * D / 4);
    for (int i = tid; i < cs; i += stride) s4[i] = ns4[i];
    for (int i = tid; i < cv; i += stride) v4[i] = nv4[i];
}

// ---------------- generic tiled SGEMM ----------------
template<bool SILU, bool HASBIAS>
__global__ __launch_bounds__(256) void sgemm_kernel(
    const float* __restrict__ A, const float* __restrict__ B,
    const float* __restrict__ bias, float* __restrict__ C,
    int M, int N, int K)
{
    const int BM = 128, BN = 64, BK = 16, TM = 8, TN = 4;
    __shared__ __align__(16) float As[BK][BM + 4];
    __shared__ __align__(16) float Bs[BK][BN];
    int t = threadIdx.x;
    int tx = t & 15;
    int ty = t >> 4;
    int m0 = blockIdx.x * BM;
    int n0 = blockIdx.y * BN;

    float acc[TM][TN];
    #pragma unroll
    for (int i = 0; i < TM; i++)
        #pragma unroll
        for (int j = 0; j < TN; j++) acc[i][j] = 0.0f;

    for (int k0 = 0; k0 < K; k0 += BK) {
        #pragma unroll
        for (int it = 0; it < 2; it++) {
            int l = t + 256 * it;
            int row = l >> 2;
            int kc = (l & 3) * 4;
            float4 v = make_float4(0.f, 0.f, 0.f, 0.f);
            int gr = m0 + row;
            if (gr < M) v = *(const float4*)&A[(size_t)gr * K + k0 + kc];
            As[kc + 0][row] = v.x;
            As[kc + 1][row] = v.y;
            As[kc + 2][row] = v.z;
            As[kc + 3][row] = v.w;
        }
        {
            int row = t >> 4;
            int nc = (t & 15) * 4;
            float4 v = *(const float4*)&B[(size_t)(k0 + row) * N + n0 + nc];
            *(float4*)&Bs[row][nc] = v;
        }
        __syncthreads();
        #pragma unroll
        for (int k = 0; k < BK; k++) {
            float4 a0 = *(float4*)&As[k][ty * TM];
            float4 a1 = *(float4*)&As[k][ty * TM + 4];
            float4 b0 = *(float4*)&Bs[k][tx * TN];
            float ar[TM] = {a0.x, a0.y, a0.z, a0.w, a1.x, a1.y, a1.z, a1.w};
            float br[TN] = {b0.x, b0.y, b0.z, b0.w};
            #pragma unroll
            for (int i = 0; i < TM; i++)
                #pragma unroll
                for (int j = 0; j < TN; j++)
                    acc[i][j] += ar[i] * br[j];
        }
        __syncthreads();
    }

    float4 bv = make_float4(0.f, 0.f, 0.f, 0.f);
    if (HASBIAS) bv = *(const float4*)&bias[n0 + tx * TN];
    #pragma unroll
    for (int i = 0; i < TM; i++) {
        int gr = m0 + ty * TM + i;
        if (gr >= M) continue;
        float4 o;
        o.x = acc[i][0] + bv.x;
        o.y = acc[i][1] + bv.y;
        o.z = acc[i][2] + bv.z;
        o.w = acc[i][3] + bv.w;
        if (SILU) { o.x = silu_f(o.x); o.y = silu_f(o.y); o.z = silu_f(o.z); o.w = silu_f(o.w); }
        *(float4*)&C[(size_t)gr * N + n0 + tx * TN] = o;
    }
}

// ---------------- dual SGEMM: C1 = A@B1, C2 = A@B2 ----------------
__global__ __launch_bounds__(256) void sgemm_dual_kernel(
    const float* __restrict__ A,
    const float* __restrict__ B1, const float* __restrict__ B2,
    float* __restrict__ C1, float* __restrict__ C2,
    int M, int N, int K)
{
    const int BM = 128, BN = 64, BK = 16, TM = 8, TN = 4;
    __shared__ __align__(16) float As[BK][BM + 4];
    __shared__ __align__(16) float Bs1[BK][BN];
    __shared__ __align__(16) float Bs2[BK][BN];
    int t = threadIdx.x;
    int tx = t & 15;
    int ty = t >> 4;
    int m0 = blockIdx.x * BM;
    int n0 = blockIdx.y * BN;

    float acc1[TM][TN], acc2[TM][TN];
    #pragma unroll
    for (int i = 0; i < TM; i++)
        #pragma unroll
        for (int j = 0; j < TN; j++) { acc1[i][j] = 0.0f; acc2[i][j] = 0.0f; }

    for (int k0 = 0; k0 < K; k0 += BK) {
        #pragma unroll
        for (int it = 0; it < 2; it++) {
            int l = t + 256 * it;
            int row = l >> 2;
            int kc = (l & 3) * 4;
            float4 v = make_float4(0.f, 0.f, 0.f, 0.f);
            int gr = m0 + row;
            if (gr < M) v = *(const float4*)&A[(size_t)gr * K + k0 + kc];
            As[kc + 0][row] = v.x;
            As[kc + 1][row] = v.y;
            As[kc + 2][row] = v.z;
            As[kc + 3][row] = v.w;
        }
        {
            int row = t >> 4;
            int nc = (t & 15) * 4;
            *(float4*)&Bs1[row][nc] = *(const float4*)&B1[(size_t)(k0 + row) * N + n0 + nc];
            *(float4*)&Bs2[row][nc] = *(const float4*)&B2[(size_t)(k0 + row) * N + n0 + nc];
        }
        __syncthreads();
        #pragma unroll
        for (int k = 0; k < BK; k++) {
            float4 a0 = *(float4*)&As[k][ty * TM];
            float4 a1 = *(float4*)&As[k][ty * TM + 4];
            float ar[TM] = {a0.x, a0.y, a0.z, a0.w, a1.x, a1.y, a1.z, a1.w};
            float4 b1 = *(float4*)&Bs1[k][tx * TN];
            float4 b2 = *(float4*)&Bs2[k][tx * TN];
            float br1[TN] = {b1.x, b1.y, b1.z, b1.w};
            float br2[TN] = {b2.x, b2.y, b2.z, b2.w};
            #pragma unroll
            for (int i = 0; i < TM; i++)
                #pragma unroll
                for (int j = 0; j < TN; j++) {
                    acc1[i][j] += ar[i] * br1[j];
                    acc2[i][j] += ar[i] * br2[j];
                }
        }
        __syncthreads();
    }

    #pragma unroll
    for (int i = 0; i < TM; i++) {
        int gr = m0 + ty * TM + i;
        if (gr >= M) continue;
        float4 o1, o2;
        o1.x = acc1[i][0]; o1.y = acc1[i][1]; o1.z = acc1[i][2]; o1.w = acc1[i][3];
        o2.x = acc2[i][0]; o2.y = acc2[i][1]; o2.z = acc2[i][2]; o2.w = acc2[i][3];
        *(float4*)&C1[(size_t)gr * N + n0 + tx * TN] = o1;
        *(float4*)&C2[(size_t)gr * N + n0 + tx * TN] = o2;
    }
}

// ---------------- fused edge kernel (v5: edge-parallel, dst-sorted, run-accumulated) ----------------
// 256 threads. Phase 1: thread t<192 owns filter cols {2t, 2t+1} (Wf 40 regs).
// Phase 2: thread t owns one float2 slot of one target: target = t>>6
// (0: messages_scalar -> g_s, 1..3: vector comp c=target-1 -> g_v), slot = t&63.
// Edges come dst-sorted via g_perm; blocks own CONTIGUOUS batch ranges so each
// thread accumulates same-dst runs in a register and flushes one red.v2 per
// dst change (~1 atomic per node per slot instead of per edge).
#define EB 16
__global__ void __launch_bounds__(256, 4) edge_kernel(
    const float* __restrict__ es_g, const float* __restrict__ ev_g,
    const float* __restrict__ norms, const int* __restrict__ eidx,
    const float* __restrict__ Wf, const float* __restrict__ bf,
    const float* __restrict__ nsv, int E, int per_block)
{
    __shared__ __align__(16) float es_sh[EB][ESZ];
    __shared__ __align__(16) float fo_sh[EB][3 * D];
    __shared__ int   src_sh[EB], dst_sh[EB];
    __shared__ float ev_sh[EB][3];
    __shared__ float fc_sh[EB];

    int t = threadIdx.x;
    bool filt = (t < 192);
    int target = t >> 6;          // 0: scalar, 1..3: vector comp target-1
    int comp = target - 1;
    int slot = t & 63;            // float2 slot (channels 2*slot, 2*slot+1)

    // Wf columns (2 consecutive) in registers
    float wf_r[ESZ][2];
    float2 bf2 = make_float2(0.f, 0.f);
    if (filt) {
        #pragma unroll
        for (int k = 0; k < ESZ; k++) {
            float2 w = *(const float2*)&Wf[k * 384 + 2 * t];
            wf_r[k][0] = w.x; wf_r[k][1] = w.y;
        }
        bf2 = *(const float2*)&bf[2 * t];
    }

    int nbatch = (E + EB - 1) / EB;
    int b0 = blockIdx.x * per_block;
    int b1 = min(b0 + per_block, nbatch);

    float2 acc = make_float2(0.f, 0.f);
    int cur_dst = -1;

    for (int b = b0; b < b1; b++) {
        int e0 = b * EB;
        int m = min(EB, E - e0);

        // ---- phase 0: stage edge data (edges in dst-sorted order) ----
        if (t < 80) {                      // es rows: 16 edges x 5 float4
            int e = t / 5, q = t % 5;
            if (e < m) {
                int eid = g_perm[e0 + e];
                ((float4*)&es_sh[e][0])[q] = __ldg(&((const float4*)&es_g[(size_t)eid * ESZ])[q]);
            }
        }
        if (t >= 128 && t < 128 + EB) {    // metadata warp
            int l = t - 128;
            if (l < m) {
                int eid = g_perm[e0 + l];
                src_sh[l] = eidx[2 * eid];
                dst_sh[l] = eidx[2 * eid + 1];
                ev_sh[l][0] = __ldg(&ev_g[3 * eid]);
                ev_sh[l][1] = __ldg(&ev_g[3 * eid + 1]);
                ev_sh[l][2] = __ldg(&ev_g[3 * eid + 2]);
                float nrm = __ldg(&norms[eid]);
                fc_sh[l] = (nrm < CUTOFF) ? 0.5f * (cospif(nrm / CUTOFF) + 1.0f) : 0.0f;
            }
        }
        __syncthreads();

        // ---- phase 1: filter_output for owned 2 cols ----
        if (filt) {
            #pragma unroll 4
            for (int e = 0; e < EB; e++) {
                if (e >= m) break;
                int src = src_sh[e];
                float2 so = __ldg((const float2*)&g_so[(size_t)src * 384 + 2 * t]);
                float ax = bf2.x, ay = bf2.y;
                #pragma unroll
                for (int k = 0; k < ESZ; k++) {
                    float ek = es_sh[e][k];
                    ax = fmaf(ek, wf_r[k][0], ax);
                    ay = fmaf(ek, wf_r[k][1], ay);
                }
                float fc = fc_sh[e];
                float2 fo;
                fo.x = ax * fc * so.x;
                fo.y = ay * fc * so.y;
                *(float2*)&fo_sh[e][2 * t] = fo;
            }
        }
        __syncthreads();

        // ---- phase 2: run-accumulate owned slot across edges ----
        if (target == 0) {
            #pragma unroll 4
            for (int e = 0; e < EB; e++) {
                if (e >= m) break;
                int dst = dst_sh[e];
                if (dst != cur_dst) {
                    if (cur_dst >= 0)
                        red_add_v2(&g_s[(size_t)cur_dst * D + 2 * slot], acc);
                    acc = make_float2(0.f, 0.f);
                    cur_dst = dst;
                }
                float2 ms = *(float2*)&fo_sh[e][2 * D + 2 * slot];
                acc.x += ms.x; acc.y += ms.y;
            }
        } else {
            #pragma unroll 4
            for (int e = 0; e < EB; e++) {
                if (e >= m) break;
                int dst = dst_sh[e];
                if (dst != cur_dst) {
                    if (cur_dst >= 0)
                        red_add_v2(&g_v[((size_t)cur_dst * 3 + comp) * D + 2 * slot], acc);
                    acc = make_float2(0.f, 0.f);
                    cur_dst = dst;
                }
                int src = src_sh[e];
                float2 gn = *(float2*)&fo_sh[e][2 * slot];
                float2 ge = *(float2*)&fo_sh[e][D + 2 * slot];
                float evc = ev_sh[e][comp];
                float2 nv = __ldg((const float2*)&nsv[((size_t)src * 3 + comp) * D + 2 * slot]);
                acc.x = fmaf(nv.x, gn.x, fmaf(ge.x, evc, acc.x));
                acc.y = fmaf(nv.y, gn.y, fmaf(ge.y, evc, acc.y));
            }
        }
        __syncthreads();
    }

    // ---- final flush ----
    if (cur_dst >= 0) {
        if (target == 0)
            red_add_v2(&g_s[(size_t)cur_dst * D + 2 * slot], acc);
        else
            red_add_v2(&g_v[((size_t)cur_dst * 3 + comp) * D + 2 * slot], acc);
    }
}

// ---------------- per-node: Vv_sq, ip, concat ----------------
__global__ void vsq_ip_cat_kernel(int n) {
    int node = blockIdx.x;
    int i = threadIdx.x;  // 128
    float vsq = 0.f, ipv = 0.f;
    #pragma unroll
    for (int c = 0; c < 3; c++) {
        float u = g_Uv[((size_t)node * 3 + c) * D + i];
        float w = g_Vv[((size_t)node * 3 + c) * D + i];
        vsq += w * w;
        ipv += u * w;
    }
    g_cat[(size_t)node * 256 + i]       = g_s[(size_t)node * D + i];
    g_cat[(size_t)node * 256 + D + i]   = vsq;
    g_ip[(size_t)node * D + i]          = ipv;
}

// ---------------- final elementwise ----------------
__global__ void final_kernel(float* __restrict__ out, int n) {
    int node = blockIdx.x;
    int i = threadIdx.x;  // 128
    const float* a = &g_a[(size_t)node * 384];
    float a_ss = a[i];
    float a_sv = a[D + i];
    float a_vv = a[2 * D + i];
    out[(size_t)node * D + i] =
        g_s[(size_t)node * D + i] + a_ss + a_sv * g_ip[(size_t)node * D + i];
    float* vout = out + (size_t)n * D;
    #pragma unroll
    for (int c = 0; c < 3; c++) {
        size_t idx = ((size_t)node * 3 + c) * D + i;
        vout[idx] = g_v[idx] + a_vv * g_Uv[idx];
    }
}

// ---------------- launch ----------------
extern "C" void kernel_launch(void* const* d_in, const int* in_sizes, int n_in,
                              void* d_out, int out_size) {
    const float* ns  = (const float*)d_in[0];
    const float* nv  = (const float*)d_in[1];
    const float* es  = (const float*)d_in[2];
    const float* ev  = (const float*)d_in[3];
    const float* en  = (const float*)d_in[4];
    const int*   ei  = (const int*)  d_in[5];
    const float* Wf  = (const float*)d_in[6];
    const float* bf  = (const float*)d_in[7];
    const float* Wm1 = (const float*)d_in[8];
    const float* bm1 = (const float*)d_in[9];
    const float* Wm2 = (const float*)d_in[10];
    const float* bm2 = (const float*)d_in[11];
    const float* WU  = (const float*)d_in[12];
    const float* WV  = (const float*)d_in[13];
    const float* Wa1 = (const float*)d_in[14];
    const float* ba1 = (const float*)d_in[15];
    const float* Wa2 = (const float*)d_in[16];
    const float* ba2 = (const float*)d_in[17];

    int n = in_sizes[0] / D;
    int E = in_sizes[4];
    float* out = (float*)d_out;

    float *p_h1, *p_so, *p_v, *p_Uv, *p_Vv, *p_cat, *p_h2, *p_a;
    cudaGetSymbolAddress((void**)&p_h1,  g_h1);
    cudaGetSymbolAddress((void**)&p_so,  g_so);
    cudaGetSymbolAddress((void**)&p_v,   g_v);
    cudaGetSymbolAddress((void**)&p_Uv,  g_Uv);
    cudaGetSymbolAddress((void**)&p_Vv,  g_Vv);
    cudaGetSymbolAddress((void**)&p_cat, g_cat);
    cudaGetSymbolAddress((void**)&p_h2,  g_h2);
    cudaGetSymbolAddress((void**)&p_a,   g_a);

    // --- CSR build (dst-sorted edge permutation) + accumulator init ---
    csr_zero_kernel<<<(n + 255) / 256, 256>>>(n);
    csr_hist_kernel<<<(E + 255) / 256, 256>>>(ei, E);
    csr_scan_kernel<<<1, 1024>>>(n);
    csr_scatter_kernel<<<(E + 255) / 256, 256>>>(ei, E);
    init_copy_kernel<<<2048, 256>>>(ns, nv, n);

    // 2. H1 = silu(ns @ Wm1 + bm1)
    {
        dim3 grid((n + 127) / 128, 128 / 64);
        sgemm_kernel<true, true><<<grid, 256>>>(ns, Wm1, bm1, p_h1, n, 128, 128);
    }
    // 3. SO = H1 @ Wm2 + bm2
    {
        dim3 grid((n + 127) / 128, 384 / 64);
        sgemm_kernel<false, true><<<grid, 256>>>(p_h1, Wm2, bm2, p_so, n, 384, 128);
    }
    // 4. fused edge kernel (dst-sorted, run-accumulated)
    {
        int nbatch = (E + EB - 1) / EB;
        int grid = 1480;
        int per_block = (nbatch + grid - 1) / grid;
        edge_kernel<<<grid, 256>>>(es, ev, en, ei, Wf, bf, nv, E, per_block);
    }
    // 5/6. Uv = v @ WU, Vv = v @ WV
    {
        dim3 grid((3 * n + 127) / 128, 128 / 64);
        sgemm_dual_kernel<<<grid, 256>>>(p_v, WU, WV, p_Uv, p_Vv, 3 * n, 128, 128);
    }
    // 7. Vv_sq, ip, cat
    vsq_ip_cat_kernel<<<n, 128>>>(n);

    // 8. H2 = silu(cat @ Wa1 + ba1)
    {
        dim3 grid((n + 127) / 128, 128 / 64);
        sgemm_kernel<true, true><<<grid, 256>>>(p_cat, Wa1, ba1, p_h2, n, 128, 256);
    }
    // 9. A = H2 @ Wa2 + ba2
    {
        dim3 grid((n + 127) / 128, 384 / 64);
        sgemm_kernel<false, true><<<grid, 256>>>(p_h2, Wa2, ba2, p_a, n, 384, 128);
    }
    // 10. final
    final_kernel<<<n, 128>>>(out, n);
}

// round 10
// speedup vs baseline: 1.5423x; 1.5423x over previous
#include <cuda_runtime.h>
#include <cuda_bf16.h>
#include <cstdio>

#define D 128
#define ESZ 20
#define MAX_NODES 20000
#define MAX_EDGES 600000
#define CUTOFF 5.0f

// ---------------- scratch (static device bss; no allocations) ----------------
__device__ __align__(16) float g_h1 [MAX_NODES * D];
__device__ __align__(16) float g_so [MAX_NODES * 3 * D];
__device__ __align__(16) float g_s  [MAX_NODES * D];
__device__ __align__(16) float g_v  [MAX_NODES * 3 * D];
__device__ __align__(16) float g_Uv [MAX_NODES * 3 * D];
__device__ __align__(16) float g_Vv [MAX_NODES * 3 * D];
__device__ __align__(16) float g_cat[MAX_NODES * 2 * D];
__device__ __align__(16) float g_ip [MAX_NODES * D];
__device__ __align__(16) float g_h2 [MAX_NODES * D];
__device__ __align__(16) float g_a  [MAX_NODES * 3 * D];

// ---------------- helpers ----------------
__device__ __forceinline__ void red_add_v4(float* addr, float4 v) {
    asm volatile("red.global.add.v4.f32 [%0], {%1, %2, %3, %4};"
                 :: "l"(addr), "f"(v.x), "f"(v.y), "f"(v.z), "f"(v.w) : "memory");
}
__device__ __forceinline__ float silu_f(float x) {
    return x / (1.0f + __expf(-x));
}

// ---------------- init: copy node states into accumulators ----------------
__global__ void init_copy_kernel(const float* __restrict__ ns, const float* __restrict__ nv, int n) {
    int tid = blockIdx.x * blockDim.x + threadIdx.x;
    int stride = gridDim.x * blockDim.x;
    const float4* ns4 = (const float4*)ns;
    const float4* nv4 = (const float4*)nv;
    float4* s4 = (float4*)g_s;
    float4* v4 = (float4*)g_v;
    int cs = n * (D / 4);
    int cv = n * (3 * D / 4);
    for (int i = tid; i < cs; i += stride) s4[i] = ns4[i];
    for (int i = tid; i < cv; i += stride) v4[i] = nv4[i];
}

// ---------------- generic tiled SGEMM ----------------
template<bool SILU, bool HASBIAS>
__global__ __launch_bounds__(256) void sgemm_kernel(
    const float* __restrict__ A, const float* __restrict__ B,
    const float* __restrict__ bias, float* __restrict__ C,
    int M, int N, int K)
{
    const int BM = 128, BN = 64, BK = 16, TM = 8, TN = 4;
    __shared__ __align__(16) float As[BK][BM + 4];
    __shared__ __align__(16) float Bs[BK][BN];
    int t = threadIdx.x;
    int tx = t & 15;
    int ty = t >> 4;
    int m0 = blockIdx.x * BM;
    int n0 = blockIdx.y * BN;

    float acc[TM][TN];
    #pragma unroll
    for (int i = 0; i < TM; i++)
        #pragma unroll
        for (int j = 0; j < TN; j++) acc[i][j] = 0.0f;

    for (int k0 = 0; k0 < K; k0 += BK) {
        #pragma unroll
        for (int it = 0; it < 2; it++) {
            int l = t + 256 * it;
            int row = l >> 2;
            int kc = (l & 3) * 4;
            float4 v = make_float4(0.f, 0.f, 0.f, 0.f);
            int gr = m0 + row;
            if (gr < M) v = *(const float4*)&A[(size_t)gr * K + k0 + kc];
            As[kc + 0][row] = v.x;
            As[kc + 1][row] = v.y;
            As[kc + 2][row] = v.z;
            As[kc + 3][row] = v.w;
        }
        {
            int row = t >> 4;
            int nc = (t & 15) * 4;
            float4 v = *(const float4*)&B[(size_t)(k0 + row) * N + n0 + nc];
            *(float4*)&Bs[row][nc] = v;
        }
        __syncthreads();
        #pragma unroll
        for (int k = 0; k < BK; k++) {
            float4 a0 = *(float4*)&As[k][ty * TM];
            float4 a1 = *(float4*)&As[k][ty * TM + 4];
            float4 b0 = *(float4*)&Bs[k][tx * TN];
            float ar[TM] = {a0.x, a0.y, a0.z, a0.w, a1.x, a1.y, a1.z, a1.w};
            float br[TN] = {b0.x, b0.y, b0.z, b0.w};
            #pragma unroll
            for (int i = 0; i < TM; i++)
                #pragma unroll
                for (int j = 0; j < TN; j++)
                    acc[i][j] += ar[i] * br[j];
        }
        __syncthreads();
    }

    float4 bv = make_float4(0.f, 0.f, 0.f, 0.f);
    if (HASBIAS) bv = *(const float4*)&bias[n0 + tx * TN];
    #pragma unroll
    for (int i = 0; i < TM; i++) {
        int gr = m0 + ty * TM + i;
        if (gr >= M) continue;
        float4 o;
        o.x = acc[i][0] + bv.x;
        o.y = acc[i][1] + bv.y;
        o.z = acc[i][2] + bv.z;
        o.w = acc[i][3] + bv.w;
        if (SILU) { o.x = silu_f(o.x); o.y = silu_f(o.y); o.z = silu_f(o.z); o.w = silu_f(o.w); }
        *(float4*)&C[(size_t)gr * N + n0 + tx * TN] = o;
    }
}

// ---------------- dual SGEMM: C1 = A@B1, C2 = A@B2 ----------------
__global__ __launch_bounds__(256) void sgemm_dual_kernel(
    const float* __restrict__ A,
    const float* __restrict__ B1, const float* __restrict__ B2,
    float* __restrict__ C1, float* __restrict__ C2,
    int M, int N, int K)
{
    const int BM = 128, BN = 64, BK = 16, TM = 8, TN = 4;
    __shared__ __align__(16) float As[BK][BM + 4];
    __shared__ __align__(16) float Bs1[BK][BN];
    __shared__ __align__(16) float Bs2[BK][BN];
    int t = threadIdx.x;
    int tx = t & 15;
    int ty = t >> 4;
    int m0 = blockIdx.x * BM;
    int n0 = blockIdx.y * BN;

    float acc1[TM][TN], acc2[TM][TN];
    #pragma unroll
    for (int i = 0; i < TM; i++)
        #pragma unroll
        for (int j = 0; j < TN; j++) { acc1[i][j] = 0.0f; acc2[i][j] = 0.0f; }

    for (int k0 = 0; k0 < K; k0 += BK) {
        #pragma unroll
        for (int it = 0; it < 2; it++) {
            int l = t + 256 * it;
            int row = l >> 2;
            int kc = (l & 3) * 4;
            float4 v = make_float4(0.f, 0.f, 0.f, 0.f);
            int gr = m0 + row;
            if (gr < M) v = *(const float4*)&A[(size_t)gr * K + k0 + kc];
            As[kc + 0][row] = v.x;
            As[kc + 1][row] = v.y;
            As[kc + 2][row] = v.z;
            As[kc + 3][row] = v.w;
        }
        {
            int row = t >> 4;
            int nc = (t & 15) * 4;
            *(float4*)&Bs1[row][nc] = *(const float4*)&B1[(size_t)(k0 + row) * N + n0 + nc];
            *(float4*)&Bs2[row][nc] = *(const float4*)&B2[(size_t)(k0 + row) * N + n0 + nc];
        }
        __syncthreads();
        #pragma unroll
        for (int k = 0; k < BK; k++) {
            float4 a0 = *(float4*)&As[k][ty * TM];
            float4 a1 = *(float4*)&As[k][ty * TM + 4];
            float ar[TM] = {a0.x, a0.y, a0.z, a0.w, a1.x, a1.y, a1.z, a1.w};
            float4 b1 = *(float4*)&Bs1[k][tx * TN];
            float4 b2 = *(float4*)&Bs2[k][tx * TN];
            float br1[TN] = {b1.x, b1.y, b1.z, b1.w};
            float br2[TN] = {b2.x, b2.y, b2.z, b2.w};
            #pragma unroll
            for (int i = 0; i < TM; i++)
                #pragma unroll
                for (int j = 0; j < TN; j++) {
                    acc1[i][j] += ar[i] * br1[j];
                    acc2[i][j] += ar[i] * br2[j];
                }
        }
        __syncthreads();
    }

    #pragma unroll
    for (int i = 0; i < TM; i++) {
        int gr = m0 + ty * TM + i;
        if (gr >= M) continue;
        float4 o1, o2;
        o1.x = acc1[i][0]; o1.y = acc1[i][1]; o1.z = acc1[i][2]; o1.w = acc1[i][3];
        o2.x = acc2[i][0]; o2.y = acc2[i][1]; o2.z = acc2[i][2]; o2.w = acc2[i][3];
        *(float4*)&C1[(size_t)gr * N + n0 + tx * TN] = o1;
        *(float4*)&C2[(size_t)gr * N + n0 + tx * TN] = o2;
    }
}

// ---------------- fused edge kernel (v6: proven v2 structure, reshaped) ----------------
// 192 threads, thread t owns filter cols {t, t+192} (Wf 40 regs -> occ 4 CTAs).
// EB=24 edges per batch. Phase 1: filter+gather -> fo_sh (same as v2).
// Phase 2: 6 groups of 32; group grp handles edges {grp, grp+6, grp+12, grp+18}
// with float4 loads + red.v4 (identical body to the 842us version).
#define EB 24
__global__ void __launch_bounds__(192, 4) edge_kernel(
    const float* __restrict__ es_g, const float* __restrict__ ev_g,
    const float* __restrict__ norms, const int* __restrict__ eidx,
    const float* __restrict__ Wf, const float* __restrict__ bf,
    const float* __restrict__ nsv, int E)
{
    __shared__ float es_sh[EB][ESZ];
    __shared__ __align__(16) float fo_sh[EB][3 * D];
    __shared__ int   src_sh[EB], dst_sh[EB];
    __shared__ float ev_sh[EB][3];
    __shared__ float fc_sh[EB];

    int t = threadIdx.x;

    // two owned Wf columns in registers (40 regs)
    float wfA[ESZ], wfB[ESZ];
    #pragma unroll
    for (int k = 0; k < ESZ; k++) {
        wfA[k] = __ldg(&Wf[k * 384 + t]);
        wfB[k] = __ldg(&Wf[k * 384 + 192 + t]);
    }
    float bfA = __ldg(&bf[t]);
    float bfB = __ldg(&bf[192 + t]);

    int nbatch = (E + EB - 1) / EB;
    for (int b = blockIdx.x; b < nbatch; b += gridDim.x) {
        int e0 = b * EB;
        int ecount = min(EB, E - e0);

        // ---- phase 0: stage edge data ----
        for (int l = t; l < EB * ESZ; l += 192) {
            int e = l / ESZ;
            es_sh[e][l % ESZ] = (e < ecount) ? __ldg(&es_g[(size_t)e0 * ESZ + l]) : 0.0f;
        }
        if (t >= 160 && t < 160 + EB) {   // warp 5 handles metadata
            int l = t - 160;
            if (l < ecount) {
                int ge_ = e0 + l;
                src_sh[l] = eidx[2 * ge_];
                dst_sh[l] = eidx[2 * ge_ + 1];
                ev_sh[l][0] = ev_g[3 * ge_];
                ev_sh[l][1] = ev_g[3 * ge_ + 1];
                ev_sh[l][2] = ev_g[3 * ge_ + 2];
                float nrm = norms[ge_];
                fc_sh[l] = (nrm < CUTOFF) ? 0.5f * (cospif(nrm / CUTOFF) + 1.0f) : 0.0f;
            } else {
                src_sh[l] = 0; dst_sh[l] = 0;
                ev_sh[l][0] = ev_sh[l][1] = ev_sh[l][2] = 0.f;
                fc_sh[l] = 0.f;
            }
        }
        __syncthreads();

        // ---- phase 1: filter_output for two owned columns ----
        #pragma unroll 4
        for (int e = 0; e < EB; e++) {
            if (e >= ecount) break;
            int src = src_sh[e];
            const float* sop = g_so + (size_t)src * 384;
            float soA = __ldg(sop + t);
            float soB = __ldg(sop + 192 + t);
            float aA = bfA, aB = bfB;
            #pragma unroll
            for (int k = 0; k < ESZ; k++) {
                float ek = es_sh[e][k];
                aA = fmaf(ek, wfA[k], aA);
                aB = fmaf(ek, wfB[k], aB);
            }
            float fc = fc_sh[e];
            fo_sh[e][t]       = aA * fc * soA;
            fo_sh[e][192 + t] = aB * fc * soB;
        }
        __syncthreads();

        // ---- phase 2: messages + scatter (identical body to v2) ----
        {
            int s = t & 31;
            int grp = t >> 5;   // 0..5
            #pragma unroll
            for (int ee = 0; ee < EB / 6; ee++) {
                int e = grp + 6 * ee;
                if (e >= ecount) continue;
                int dst = dst_sh[e];
                int src = src_sh[e];
                float4 gn = *(float4*)&fo_sh[e][4 * s];
                float4 ge = *(float4*)&fo_sh[e][D + 4 * s];
                float4 ms = *(float4*)&fo_sh[e][2 * D + 4 * s];
                red_add_v4(&g_s[(size_t)dst * D + 4 * s], ms);
                #pragma unroll
                for (int c = 0; c < 3; c++) {
                    float evc = ev_sh[e][c];
                    float4 nv = __ldg((const float4*)&nsv[((size_t)src * 3 + c) * D + 4 * s]);
                    float4 mv;
                    mv.x = fmaf(nv.x, gn.x, ge.x * evc);
                    mv.y = fmaf(nv.y, gn.y, ge.y * evc);
                    mv.z = fmaf(nv.z, gn.z, ge.z * evc);
                    mv.w = fmaf(nv.w, gn.w, ge.w * evc);
                    red_add_v4(&g_v[((size_t)dst * 3 + c) * D + 4 * s], mv);
                }
            }
        }
        __syncthreads();
    }
}

// ---------------- per-node: Vv_sq, ip, concat ----------------
__global__ void vsq_ip_cat_kernel(int n) {
    int node = blockIdx.x;
    int i = threadIdx.x;  // 128
    float vsq = 0.f, ipv = 0.f;
    #pragma unroll
    for (int c = 0; c < 3; c++) {
        float u = g_Uv[((size_t)node * 3 + c) * D + i];
        float w = g_Vv[((size_t)node * 3 + c) * D + i];
        vsq += w * w;
        ipv += u * w;
    }
    g_cat[(size_t)node * 256 + i]       = g_s[(size_t)node * D + i];
    g_cat[(size_t)node * 256 + D + i]   = vsq;
    g_ip[(size_t)node * D + i]          = ipv;
}

// ---------------- final elementwise ----------------
__global__ void final_kernel(float* __restrict__ out, int n) {
    int node = blockIdx.x;
    int i = threadIdx.x;  // 128
    const float* a = &g_a[(size_t)node * 384];
    float a_ss = a[i];
    float a_sv = a[D + i];
    float a_vv = a[2 * D + i];
    out[(size_t)node * D + i] =
        g_s[(size_t)node * D + i] + a_ss + a_sv * g_ip[(size_t)node * D + i];
    float* vout = out + (size_t)n * D;
    #pragma unroll
    for (int c = 0; c < 3; c++) {
        size_t idx = ((size_t)node * 3 + c) * D + i;
        vout[idx] = g_v[idx] + a_vv * g_Uv[idx];
    }
}

// ---------------- launch ----------------
extern "C" void kernel_launch(void* const* d_in, const int* in_sizes, int n_in,
                              void* d_out, int out_size) {
    const float* ns  = (const float*)d_in[0];
    const float* nv  = (const float*)d_in[1];
    const float* es  = (const float*)d_in[2];
    const float* ev  = (const float*)d_in[3];
    const float* en  = (const float*)d_in[4];
    const int*   ei  = (const int*)  d_in[5];
    const float* Wf  = (const float*)d_in[6];
    const float* bf  = (const float*)d_in[7];
    const float* Wm1 = (const float*)d_in[8];
    const float* bm1 = (const float*)d_in[9];
    const float* Wm2 = (const float*)d_in[10];
    const float* bm2 = (const float*)d_in[11];
    const float* WU  = (const float*)d_in[12];
    const float* WV  = (const float*)d_in[13];
    const float* Wa1 = (const float*)d_in[14];
    const float* ba1 = (const float*)d_in[15];
    const float* Wa2 = (const float*)d_in[16];
    const float* ba2 = (const float*)d_in[17];

    int n = in_sizes[0] / D;
    int E = in_sizes[4];
    float* out = (float*)d_out;

    float *p_h1, *p_so, *p_v, *p_Uv, *p_Vv, *p_cat, *p_h2, *p_a;
    cudaGetSymbolAddress((void**)&p_h1,  g_h1);
    cudaGetSymbolAddress((void**)&p_so,  g_so);
    cudaGetSymbolAddress((void**)&p_v,   g_v);
    cudaGetSymbolAddress((void**)&p_Uv,  g_Uv);
    cudaGetSymbolAddress((void**)&p_Vv,  g_Vv);
    cudaGetSymbolAddress((void**)&p_cat, g_cat);
    cudaGetSymbolAddress((void**)&p_h2,  g_h2);
    cudaGetSymbolAddress((void**)&p_a,   g_a);

    // 1. init accumulators s = ns, v = nv
    init_copy_kernel<<<2048, 256>>>(ns, nv, n);

    // 2. H1 = silu(ns @ Wm1 + bm1)
    {
        dim3 grid((n + 127) / 128, 128 / 64);
        sgemm_kernel<true, true><<<grid, 256>>>(ns, Wm1, bm1, p_h1, n, 128, 128);
    }
    // 3. SO = H1 @ Wm2 + bm2
    {
        dim3 grid((n + 127) / 128, 384 / 64);
        sgemm_kernel<false, true><<<grid, 256>>>(p_h1, Wm2, bm2, p_so, n, 384, 128);
    }
    // 4. fused edge kernel
    {
        int nbatch = (E + EB - 1) / EB;
        int grid = nbatch < 2368 ? nbatch : 2368;   // 148 SMs x 4 CTAs x 4 waves
        edge_kernel<<<grid, 192>>>(es, ev, en, ei, Wf, bf, nv, E);
    }
    // 5/6. Uv = v @ WU, Vv = v @ WV
    {
        dim3 grid((3 * n + 127) / 128, 128 / 64);
        sgemm_dual_kernel<<<grid, 256>>>(p_v, WU, WV, p_Uv, p_Vv, 3 * n, 128, 128);
    }
    // 7. Vv_sq, ip, cat
    vsq_ip_cat_kernel<<<n, 128>>>(n);

    // 8. H2 = silu(cat @ Wa1 + ba1)
    {
        dim3 grid((n + 127) / 128, 128 / 64);
        sgemm_kernel<true, true><<<grid, 256>>>(p_cat, Wa1, ba1, p_h2, n, 128, 256);
    }
    // 9. A = H2 @ Wa2 + ba2
    {
        dim3 grid((n + 127) / 128, 384 / 64);
        sgemm_kernel<false, true><<<grid, 256>>>(p_h2, Wa2, ba2, p_a, n, 384, 128);
    }
    // 10. final
    final_kernel<<<n, 128>>>(out, n);
}

// round 12
// speedup vs baseline: 1.5935x; 1.0332x over previous
#include <cuda_runtime.h>
#include <cuda_bf16.h>
#include <cstdio>

#define D 128
#define ESZ 20
#define MAX_NODES 20000
#define MAX_EDGES 600000
#define CUTOFF 5.0f

// ---------------- scratch (static device bss; no allocations) ----------------
__device__ __align__(16) float g_h1 [MAX_NODES * D];
__device__ __align__(16) float g_so [MAX_NODES * 3 * D];
__device__ __align__(16) float g_s  [MAX_NODES * D];
__device__ __align__(16) float g_v  [MAX_NODES * 3 * D];
__device__ __align__(16) float g_Uv [MAX_NODES * 3 * D];
__device__ __align__(16) float g_Vv [MAX_NODES * 3 * D];
__device__ __align__(16) float g_cat[MAX_NODES * 2 * D];
__device__ __align__(16) float g_ip [MAX_NODES * D];
__device__ __align__(16) float g_h2 [MAX_NODES * D];
__device__ __align__(16) float g_a  [MAX_NODES * 3 * D];

// ---------------- helpers ----------------
__device__ __forceinline__ void red_add_v4(float* addr, float4 v) {
    asm volatile("red.global.add.v4.f32 [%0], {%1, %2, %3, %4};"
                 :: "l"(addr), "f"(v.x), "f"(v.y), "f"(v.z), "f"(v.w) : "memory");
}
__device__ __forceinline__ float silu_f(float x) {
    return x / (1.0f + __expf(-x));
}

// ---------------- init: copy node states into accumulators ----------------
__global__ void init_copy_kernel(const float* __restrict__ ns, const float* __restrict__ nv, int n) {
    int tid = blockIdx.x * blockDim.x + threadIdx.x;
    int stride = gridDim.x * blockDim.x;
    const float4* ns4 = (const float4*)ns;
    const float4* nv4 = (const float4*)nv;
    float4* s4 = (float4*)g_s;
    float4* v4 = (float4*)g_v;
    int cs = n * (D / 4);
    int cv = n * (3 * D / 4);
    for (int i = tid; i < cs; i += stride) s4[i] = ns4[i];
    for (int i = tid; i < cv; i += stride) v4[i] = nv4[i];
}

// ---------------- generic tiled SGEMM ----------------
template<bool SILU, bool HASBIAS>
__global__ __launch_bounds__(256) void sgemm_kernel(
    const float* __restrict__ A, const float* __restrict__ B,
    const float* __restrict__ bias, float* __restrict__ C,
    int M, int N, int K)
{
    const int BM = 128, BN = 64, BK = 16, TM = 8, TN = 4;
    __shared__ __align__(16) float As[BK][BM + 4];
    __shared__ __align__(16) float Bs[BK][BN];
    int t = threadIdx.x;
    int tx = t & 15;
    int ty = t >> 4;
    int m0 = blockIdx.x * BM;
    int n0 = blockIdx.y * BN;

    float acc[TM][TN];
    #pragma unroll
    for (int i = 0; i < TM; i++)
        #pragma unroll
        for (int j = 0; j < TN; j++) acc[i][j] = 0.0f;

    for (int k0 = 0; k0 < K; k0 += BK) {
        #pragma unroll
        for (int it = 0; it < 2; it++) {
            int l = t + 256 * it;
            int row = l >> 2;
            int kc = (l & 3) * 4;
            float4 v = make_float4(0.f, 0.f, 0.f, 0.f);
            int gr = m0 + row;
            if (gr < M) v = *(const float4*)&A[(size_t)gr * K + k0 + kc];
            As[kc + 0][row] = v.x;
            As[kc + 1][row] = v.y;
            As[kc + 2][row] = v.z;
            As[kc + 3][row] = v.w;
        }
        {
            int row = t >> 4;
            int nc = (t & 15) * 4;
            float4 v = *(const float4*)&B[(size_t)(k0 + row) * N + n0 + nc];
            *(float4*)&Bs[row][nc] = v;
        }
        __syncthreads();
        #pragma unroll
        for (int k = 0; k < BK; k++) {
            float4 a0 = *(float4*)&As[k][ty * TM];
            float4 a1 = *(float4*)&As[k][ty * TM + 4];
            float4 b0 = *(float4*)&Bs[k][tx * TN];
            float ar[TM] = {a0.x, a0.y, a0.z, a0.w, a1.x, a1.y, a1.z, a1.w};
            float br[TN] = {b0.x, b0.y, b0.z, b0.w};
            #pragma unroll
            for (int i = 0; i < TM; i++)
                #pragma unroll
                for (int j = 0; j < TN; j++)
                    acc[i][j] += ar[i] * br[j];
        }
        __syncthreads();
    }

    float4 bv = make_float4(0.f, 0.f, 0.f, 0.f);
    if (HASBIAS) bv = *(const float4*)&bias[n0 + tx * TN];
    #pragma unroll
    for (int i = 0; i < TM; i++) {
        int gr = m0 + ty * TM + i;
        if (gr >= M) continue;
        float4 o;
        o.x = acc[i][0] + bv.x;
        o.y = acc[i][1] + bv.y;
        o.z = acc[i][2] + bv.z;
        o.w = acc[i][3] + bv.w;
        if (SILU) { o.x = silu_f(o.x); o.y = silu_f(o.y); o.z = silu_f(o.z); o.w = silu_f(o.w); }
        *(float4*)&C[(size_t)gr * N + n0 + tx * TN] = o;
    }
}

// ---------------- dual SGEMM: C1 = A@B1, C2 = A@B2 ----------------
__global__ __launch_bounds__(256) void sgemm_dual_kernel(
    const float* __restrict__ A,
    const float* __restrict__ B1, const float* __restrict__ B2,
    float* __restrict__ C1, float* __restrict__ C2,
    int M, int N, int K)
{
    const int BM = 128, BN = 64, BK = 16, TM = 8, TN = 4;
    __shared__ __align__(16) float As[BK][BM + 4];
    __shared__ __align__(16) float Bs1[BK][BN];
    __shared__ __align__(16) float Bs2[BK][BN];
    int t = threadIdx.x;
    int tx = t & 15;
    int ty = t >> 4;
    int m0 = blockIdx.x * BM;
    int n0 = blockIdx.y * BN;

    float acc1[TM][TN], acc2[TM][TN];
    #pragma unroll
    for (int i = 0; i < TM; i++)
        #pragma unroll
        for (int j = 0; j < TN; j++) { acc1[i][j] = 0.0f; acc2[i][j] = 0.0f; }

    for (int k0 = 0; k0 < K; k0 += BK) {
        #pragma unroll
        for (int it = 0; it < 2; it++) {
            int l = t + 256 * it;
            int row = l >> 2;
            int kc = (l & 3) * 4;
            float4 v = make_float4(0.f, 0.f, 0.f, 0.f);
            int gr = m0 + row;
            if (gr < M) v = *(const float4*)&A[(size_t)gr * K + k0 + kc];
            As[kc + 0][row] = v.x;
            As[kc + 1][row] = v.y;
            As[kc + 2][row] = v.z;
            As[kc + 3][row] = v.w;
        }
        {
            int row = t >> 4;
            int nc = (t & 15) * 4;
            *(float4*)&Bs1[row][nc] = *(const float4*)&B1[(size_t)(k0 + row) * N + n0 + nc];
            *(float4*)&Bs2[row][nc] = *(const float4*)&B2[(size_t)(k0 + row) * N + n0 + nc];
        }
        __syncthreads();
        #pragma unroll
        for (int k = 0; k < BK; k++) {
            float4 a0 = *(float4*)&As[k][ty * TM];
            float4 a1 = *(float4*)&As[k][ty * TM + 4];
            float ar[TM] = {a0.x, a0.y, a0.z, a0.w, a1.x, a1.y, a1.z, a1.w};
            float4 b1 = *(float4*)&Bs1[k][tx * TN];
            float4 b2 = *(float4*)&Bs2[k][tx * TN];
            float br1[TN] = {b1.x, b1.y, b1.z, b1.w};
            float br2[TN] = {b2.x, b2.y, b2.z, b2.w};
            #pragma unroll
            for (int i = 0; i < TM; i++)
                #pragma unroll
                for (int j = 0; j < TN; j++) {
                    acc1[i][j] += ar[i] * br1[j];
                    acc2[i][j] += ar[i] * br2[j];
                }
        }
        __syncthreads();
    }

    #pragma unroll
    for (int i = 0; i < TM; i++) {
        int gr = m0 + ty * TM + i;
        if (gr >= M) continue;
        float4 o1, o2;
        o1.x = acc1[i][0]; o1.y = acc1[i][1]; o1.z = acc1[i][2]; o1.w = acc1[i][3];
        o2.x = acc2[i][0]; o2.y = acc2[i][1]; o2.z = acc2[i][2]; o2.w = acc2[i][3];
        *(float4*)&C1[(size_t)gr * N + n0 + tx * TN] = o1;
        *(float4*)&C2[(size_t)gr * N + n0 + tx * TN] = o2;
    }
}

// ---------------- fused edge kernel (v7: v6 + vectorized es/so/fo) ----------------
// 192 threads, thread t owns filter cols {2t, 2t+1} (Wf 40 regs as float2).
// es read as float4 (5 LDS.128/edge instead of 20 LDS.32). so = 1 LDG.64,
// fo = 1 STS.64. Phase 2 identical to proven v2/v6 body.
#define EB 24
__global__ void __launch_bounds__(192, 4) edge_kernel(
    const float* __restrict__ es_g, const float* __restrict__ ev_g,
    const float* __restrict__ norms, const int* __restrict__ eidx,
    const float* __restrict__ Wf, const float* __restrict__ bf,
    const float* __restrict__ nsv, int E)
{
    __shared__ __align__(16) float es_sh[EB][ESZ];     // 80B rows, 16B-aligned
    __shared__ __align__(16) float fo_sh[EB][3 * D];
    __shared__ int   src_sh[EB], dst_sh[EB];
    __shared__ float ev_sh[EB][3];
    __shared__ float fc_sh[EB];

    int t = threadIdx.x;

    // two consecutive Wf columns in registers (float2 x 20 = 40 regs)
    float2 wf[ESZ];
    #pragma unroll
    for (int k = 0; k < ESZ; k++)
        wf[k] = *(const float2*)&Wf[k * 384 + 2 * t];
    float2 bf2 = *(const float2*)&bf[2 * t];

    int nbatch = (E + EB - 1) / EB;
    for (int b = blockIdx.x; b < nbatch; b += gridDim.x) {
        int e0 = b * EB;
        int ecount = min(EB, E - e0);

        // ---- phase 0: stage edge data (vectorized) ----
        if (t < EB * 5) {                  // 120 float4 transfers
            int e = t / 5, q = t % 5;
            if (e < ecount)
                ((float4*)&es_sh[e][0])[q] =
                    __ldg(&((const float4*)&es_g[(size_t)(e0 + e) * ESZ])[q]);
        }
        if (t >= 160 && t < 160 + EB) {    // warp 5 handles metadata
            int l = t - 160;
            if (l < ecount) {
                int ge_ = e0 + l;
                src_sh[l] = eidx[2 * ge_];
                dst_sh[l] = eidx[2 * ge_ + 1];
                ev_sh[l][0] = ev_g[3 * ge_];
                ev_sh[l][1] = ev_g[3 * ge_ + 1];
                ev_sh[l][2] = ev_g[3 * ge_ + 2];
                float nrm = norms[ge_];
                fc_sh[l] = (nrm < CUTOFF) ? 0.5f * (cospif(nrm / CUTOFF) + 1.0f) : 0.0f;
            } else {
                src_sh[l] = 0; dst_sh[l] = 0;
                ev_sh[l][0] = ev_sh[l][1] = ev_sh[l][2] = 0.f;
                fc_sh[l] = 0.f;
            }
        }
        __syncthreads();

        // ---- phase 1: filter_output for two owned columns ----
        #pragma unroll 4
        for (int e = 0; e < EB; e++) {
            if (e >= ecount) break;
            int src = src_sh[e];
            float2 so = __ldg((const float2*)&g_so[(size_t)src * 384 + 2 * t]);
            float ax = bf2.x, ay = bf2.y;
            #pragma unroll
            for (int q = 0; q < 5; q++) {
                float4 e4 = *(const float4*)&es_sh[e][4 * q];
                ax = fmaf(e4.x, wf[4 * q + 0].x, ax);
                ay = fmaf(e4.x, wf[4 * q + 0].y, ay);
                ax = fmaf(e4.y, wf[4 * q + 1].x, ax);
                ay = fmaf(e4.y, wf[4 * q + 1].y, ay);
                ax = fmaf(e4.z, wf[4 * q + 2].x, ax);
                ay = fmaf(e4.z, wf[4 * q + 2].y, ay);
                ax = fmaf(e4.w, wf[4 * q + 3].x, ax);
                ay = fmaf(e4.w, wf[4 * q + 3].y, ay);
            }
            float fc = fc_sh[e];
            float2 fo;
            fo.x = ax * fc * so.x;
            fo.y = ay * fc * so.y;
            *(float2*)&fo_sh[e][2 * t] = fo;
        }
        __syncthreads();

        // ---- phase 2: messages + scatter (identical body to v6) ----
        {
            int s = t & 31;
            int grp = t >> 5;   // 0..5
            #pragma unroll
            for (int ee = 0; ee < EB / 6; ee++) {
                int e = grp + 6 * ee;
                if (e >= ecount) continue;
                int dst = dst_sh[e];
                int src = src_sh[e];
                float4 gn = *(float4*)&fo_sh[e][4 * s];
                float4 ge = *(float4*)&fo_sh[e][D + 4 * s];
                float4 ms = *(float4*)&fo_sh[e][2 * D + 4 * s];
                red_add_v4(&g_s[(size_t)dst * D + 4 * s], ms);
                #pragma unroll
                for (int c = 0; c < 3; c++) {
                    float evc = ev_sh[e][c];
                    float4 nv = __ldg((const float4*)&nsv[((size_t)src * 3 + c) * D + 4 * s]);
                    float4 mv;
                    mv.x = fmaf(nv.x, gn.x, ge.x * evc);
                    mv.y = fmaf(nv.y, gn.y, ge.y * evc);
                    mv.z = fmaf(nv.z, gn.z, ge.z * evc);
                    mv.w = fmaf(nv.w, gn.w, ge.w * evc);
                    red_add_v4(&g_v[((size_t)dst * 3 + c) * D + 4 * s], mv);
                }
            }
        }
        __syncthreads();
    }
}

// ---------------- per-node: Vv_sq, ip, concat ----------------
__global__ void vsq_ip_cat_kernel(int n) {
    int node = blockIdx.x;
    int i = threadIdx.x;  // 128
    float vsq = 0.f, ipv = 0.f;
    #pragma unroll
    for (int c = 0; c < 3; c++) {
        float u = g_Uv[((size_t)node * 3 + c) * D + i];
        float w = g_Vv[((size_t)node * 3 + c) * D + i];
        vsq += w * w;
        ipv += u * w;
    }
    g_cat[(size_t)node * 256 + i]       = g_s[(size_t)node * D + i];
    g_cat[(size_t)node * 256 + D + i]   = vsq;
    g_ip[(size_t)node * D + i]          = ipv;
}

// ---------------- final elementwise ----------------
__global__ void final_kernel(float* __restrict__ out, int n) {
    int node = blockIdx.x;
    int i = threadIdx.x;  // 128
    const float* a = &g_a[(size_t)node * 384];
    float a_ss = a[i];
    float a_sv = a[D + i];
    float a_vv = a[2 * D + i];
    out[(size_t)node * D + i] =
        g_s[(size_t)node * D + i] + a_ss + a_sv * g_ip[(size_t)node * D + i];
    float* vout = out + (size_t)n * D;
    #pragma unroll
    for (int c = 0; c < 3; c++) {
        size_t idx = ((size_t)node * 3 + c) * D + i;
        vout[idx] = g_v[idx] + a_vv * g_Uv[idx];
    }
}

// ---------------- launch ----------------
extern "C" void kernel_launch(void* const* d_in, const int* in_sizes, int n_in,
                              void* d_out, int out_size) {
    const float* ns  = (const float*)d_in[0];
    const float* nv  = (const float*)d_in[1];
    const float* es  = (const float*)d_in[2];
    const float* ev  = (const float*)d_in[3];
    const float* en  = (const float*)d_in[4];
    const int*   ei  = (const int*)  d_in[5];
    const float* Wf  = (const float*)d_in[6];
    const float* bf  = (const float*)d_in[7];
    const float* Wm1 = (const float*)d_in[8];
    const float* bm1 = (const float*)d_in[9];
    const float* Wm2 = (const float*)d_in[10];
    const float* bm2 = (const float*)d_in[11];
    const float* WU  = (const float*)d_in[12];
    const float* WV  = (const float*)d_in[13];
    const float* Wa1 = (const float*)d_in[14];
    const float* ba1 = (const float*)d_in[15];
    const float* Wa2 = (const float*)d_in[16];
    const float* ba2 = (const float*)d_in[17];

    int n = in_sizes[0] / D;
    int E = in_sizes[4];
    float* out = (float*)d_out;

    float *p_h1, *p_so, *p_v, *p_Uv, *p_Vv, *p_cat, *p_h2, *p_a;
    cudaGetSymbolAddress((void**)&p_h1,  g_h1);
    cudaGetSymbolAddress((void**)&p_so,  g_so);
    cudaGetSymbolAddress((void**)&p_v,   g_v);
    cudaGetSymbolAddress((void**)&p_Uv,  g_Uv);
    cudaGetSymbolAddress((void**)&p_Vv,  g_Vv);
    cudaGetSymbolAddress((void**)&p_cat, g_cat);
    cudaGetSymbolAddress((void**)&p_h2,  g_h2);
    cudaGetSymbolAddress((void**)&p_a,   g_a);

    // 1. init accumulators s = ns, v = nv
    init_copy_kernel<<<2048, 256>>>(ns, nv, n);

    // 2. H1 = silu(ns @ Wm1 + bm1)
    {
        dim3 grid((n + 127) / 128, 128 / 64);
        sgemm_kernel<true, true><<<grid, 256>>>(ns, Wm1, bm1, p_h1, n, 128, 128);
    }
    // 3. SO = H1 @ Wm2 + bm2
    {
        dim3 grid((n + 127) / 128, 384 / 64);
        sgemm_kernel<false, true><<<grid, 256>>>(p_h1, Wm2, bm2, p_so, n, 384, 128);
    }
    // 4. fused edge kernel
    {
        int nbatch = (E + EB - 1) / EB;
        int grid = nbatch < 2368 ? nbatch : 2368;
        edge_kernel<<<grid, 192>>>(es, ev, en, ei, Wf, bf, nv, E);
    }
    // 5/6. Uv = v @ WU, Vv = v @ WV
    {
        dim3 grid((3 * n + 127) / 128, 128 / 64);
        sgemm_dual_kernel<<<grid, 256>>>(p_v, WU, WV, p_Uv, p_Vv, 3 * n, 128, 128);
    }
    // 7. Vv_sq, ip, cat
    vsq_ip_cat_kernel<<<n, 128>>>(n);

    // 8. H2 = silu(cat @ Wa1 + ba1)
    {
        dim3 grid((n + 127) / 128, 128 / 64);
        sgemm_kernel<true, true><<<grid, 256>>>(p_cat, Wa1, ba1, p_h2, n, 128, 256);
    }
    // 9. A = H2 @ Wa2 + ba2
    {
        dim3 grid((n + 127) / 128, 384 / 64);
        sgemm_kernel<false, true><<<grid, 256>>>(p_h2, Wa2, ba2, p_a, n, 384, 128);
    }
    // 10. final
    final_kernel<<<n, 128>>>(out, n);
}

// round 13
// speedup vs baseline: 1.8628x; 1.1690x over previous
#include <cuda_runtime.h>
#include <cuda_bf16.h>
#include <cstdio>
#include <cstdint>

#define D 128
#define ESZ 20
#define MAX_NODES 20000
#define MAX_EDGES 600000
#define CUTOFF 5.0f

// ---------------- scratch (static device bss; no allocations) ----------------
__device__ __align__(16) float g_h1 [MAX_NODES * D];
__device__ __align__(16) float g_so [MAX_NODES * 3 * D];
__device__ __align__(16) float g_s  [MAX_NODES * D];
__device__ __align__(16) float g_v  [MAX_NODES * 3 * D];
__device__ __align__(16) float g_Uv [MAX_NODES * 3 * D];
__device__ __align__(16) float g_Vv [MAX_NODES * 3 * D];
__device__ __align__(16) float g_cat[MAX_NODES * 2 * D];
__device__ __align__(16) float g_ip [MAX_NODES * D];
__device__ __align__(16) float g_h2 [MAX_NODES * D];
__device__ __align__(16) float g_a  [MAX_NODES * 3 * D];

// ---------------- helpers ----------------
__device__ __forceinline__ void red_add_v4(float* addr, float4 v) {
    asm volatile("red.global.add.v4.f32 [%0], {%1, %2, %3, %4};"
                 :: "l"(addr), "f"(v.x), "f"(v.y), "f"(v.z), "f"(v.w) : "memory");
}
__device__ __forceinline__ void red_add_v2(float* addr, float2 v) {
    asm volatile("red.global.add.v2.f32 [%0], {%1, %2};"
                 :: "l"(addr), "f"(v.x), "f"(v.y) : "memory");
}
__device__ __forceinline__ float silu_f(float x) {
    return x / (1.0f + __expf(-x));
}
__device__ __forceinline__ uint32_t f2tf32(float f) {
    uint32_t r;
    asm("cvt.rna.tf32.f32 %0, %1;" : "=r"(r) : "f"(f));
    return r;
}
__device__ __forceinline__ void mma_tf32(float c[4],
    uint32_t a0, uint32_t a1, uint32_t a2, uint32_t a3,
    uint32_t b0, uint32_t b1)
{
    asm volatile(
        "mma.sync.aligned.m16n8k8.row.col.f32.tf32.tf32.f32 "
        "{%0,%1,%2,%3}, {%4,%5,%6,%7}, {%8,%9}, {%0,%1,%2,%3};"
        : "+f"(c[0]), "+f"(c[1]), "+f"(c[2]), "+f"(c[3])
        : "r"(a0), "r"(a1), "r"(a2), "r"(a3), "r"(b0), "r"(b1));
}

// ---------------- init: copy node states into accumulators ----------------
__global__ void init_copy_kernel(const float* __restrict__ ns, const float* __restrict__ nv, int n) {
    int tid = blockIdx.x * blockDim.x + threadIdx.x;
    int stride = gridDim.x * blockDim.x;
    const float4* ns4 = (const float4*)ns;
    const float4* nv4 = (const float4*)nv;
    float4* s4 = (float4*)g_s;
    float4* v4 = (float4*)g_v;
    int cs = n * (D / 4);
    int cv = n * (3 * D / 4);
    for (int i = tid; i < cs; i += stride) s4[i] = ns4[i];
    for (int i = tid; i < cv; i += stride) v4[i] = nv4[i];
}

// ---------------- tf32 tensor-core GEMM: C = act(A[MxK] @ B[KxN] + bias) ----------------
// BM=128, BN=64, BK=16, 256 threads (8 warps). Warp (wm 0..3, wn 0..1) owns a
// 32x32 tile = 2 (m16) x 4 (n8) mma.m16n8k8 tiles. K % 16 == 0, N % 64 == 0.
template<bool SILU, bool HASBIAS>
__global__ __launch_bounds__(256) void mma_gemm_kernel(
    const float* __restrict__ A, const float* __restrict__ B,
    const float* __restrict__ bias, float* __restrict__ C,
    int M, int N, int K)
{
    const int BM = 128, BN = 64, BK = 16;
    __shared__ __align__(16) float As[BK][BM + 8];   // 136 words: conflict-free frag loads
    __shared__ __align__(16) float Bs[BK][BN + 8];   // 72 words
    int t = threadIdx.x;
    int lane = t & 31;
    int warp = t >> 5;
    int g = lane >> 2;        // groupID 0..7
    int tig = lane & 3;       // thread-in-group 0..3
    int wm = warp & 3;        // 0..3 (m)
    int wn = warp >> 2;       // 0..1 (n)
    int m0 = blockIdx.x * BM;
    int n0 = blockIdx.y * BN;

    float c[2][4][4];
    #pragma unroll
    for (int mt = 0; mt < 2; mt++)
        #pragma unroll
        for (int nt = 0; nt < 4; nt++)
            #pragma unroll
            for (int i = 0; i < 4; i++) c[mt][nt][i] = 0.0f;

    for (int k0 = 0; k0 < K; k0 += BK) {
        // stage A tile (128x16), transposed to As[k][m]
        #pragma unroll
        for (int it = 0; it < 2; it++) {
            int l = t + 256 * it;
            int row = l >> 2;
            int kc = (l & 3) * 4;
            float4 v = make_float4(0.f, 0.f, 0.f, 0.f);
            int gr = m0 + row;
            if (gr < M) v = *(const float4*)&A[(size_t)gr * K + k0 + kc];
            As[kc + 0][row] = v.x;
            As[kc + 1][row] = v.y;
            As[kc + 2][row] = v.z;
            As[kc + 3][row] = v.w;
        }
        // stage B tile (16x64), row-major
        {
            int row = t >> 4;
            int nc = (t & 15) * 4;
            *(float4*)&Bs[row][nc] = *(const float4*)&B[(size_t)(k0 + row) * N + n0 + nc];
        }
        __syncthreads();

        #pragma unroll
        for (int k8 = 0; k8 < BK; k8 += 8) {
            uint32_t a[2][4];
            #pragma unroll
            for (int mt = 0; mt < 2; mt++) {
                int mrow = wm * 32 + mt * 16;
                a[mt][0] = f2tf32(As[k8 + tig][mrow + g]);
                a[mt][1] = f2tf32(As[k8 + tig][mrow + g + 8]);
                a[mt][2] = f2tf32(As[k8 + tig + 4][mrow + g]);
                a[mt][3] = f2tf32(As[k8 + tig + 4][mrow + g + 8]);
            }
            uint32_t b[4][2];
            #pragma unroll
            for (int nt = 0; nt < 4; nt++) {
                int ncol = wn * 32 + nt * 8;
                b[nt][0] = f2tf32(Bs[k8 + tig][ncol + g]);
                b[nt][1] = f2tf32(Bs[k8 + tig + 4][ncol + g]);
            }
            #pragma unroll
            for (int mt = 0; mt < 2; mt++)
                #pragma unroll
                for (int nt = 0; nt < 4; nt++)
                    mma_tf32(c[mt][nt], a[mt][0], a[mt][1], a[mt][2], a[mt][3],
                             b[nt][0], b[nt][1]);
        }
        __syncthreads();
    }

    // epilogue
    #pragma unroll
    for (int mt = 0; mt < 2; mt++) {
        #pragma unroll
        for (int nt = 0; nt < 4; nt++) {
            int row0 = m0 + wm * 32 + mt * 16 + g;
            int row1 = row0 + 8;
            int col = n0 + wn * 32 + nt * 8 + 2 * tig;
            float2 bv = make_float2(0.f, 0.f);
            if (HASBIAS) bv = *(const float2*)&bias[col];
            if (row0 < M) {
                float2 o;
                o.x = c[mt][nt][0] + bv.x;
                o.y = c[mt][nt][1] + bv.y;
                if (SILU) { o.x = silu_f(o.x); o.y = silu_f(o.y); }
                *(float2*)&C[(size_t)row0 * N + col] = o;
            }
            if (row1 < M) {
                float2 o;
                o.x = c[mt][nt][2] + bv.x;
                o.y = c[mt][nt][3] + bv.y;
                if (SILU) { o.x = silu_f(o.x); o.y = silu_f(o.y); }
                *(float2*)&C[(size_t)row1 * N + col] = o;
            }
        }
    }
}

// ---------------- fused edge kernel (v8: v7 + direct ms reduction) ----------------
// 192 threads, thread t owns filter cols {2t, 2t+1} (Wf 40 regs as float2).
// t <  128: cols in gn/ge segments -> STS.64 to fo_sh.
// t >= 128: cols in ms segment [256,384) -> red.v2 straight to g_s (no smem trip).
// Phase 2 handles only the vector messages (gn/ge from smem).
#define EB 24
__global__ void __launch_bounds__(192, 4) edge_kernel(
    const float* __restrict__ es_g, const float* __restrict__ ev_g,
    const float* __restrict__ norms, const int* __restrict__ eidx,
    const float* __restrict__ Wf, const float* __restrict__ bf,
    const float* __restrict__ nsv, int E)
{
    __shared__ __align__(16) float es_sh[EB][ESZ];     // 80B rows, 16B-aligned
    __shared__ __align__(16) float fo_sh[EB][2 * D];   // gn[128], ge[128]
    __shared__ int   src_sh[EB], dst_sh[EB];
    __shared__ float ev_sh[EB][3];
    __shared__ float fc_sh[EB];

    int t = threadIdx.x;

    // two consecutive Wf columns in registers (float2 x 20 = 40 regs)
    float2 wf[ESZ];
    #pragma unroll
    for (int k = 0; k < ESZ; k++)
        wf[k] = *(const float2*)&Wf[k * 384 + 2 * t];
    float2 bf2 = *(const float2*)&bf[2 * t];

    int nbatch = (E + EB - 1) / EB;
    for (int b = blockIdx.x; b < nbatch; b += gridDim.x) {
        int e0 = b * EB;
        int ecount = min(EB, E - e0);

        // ---- phase 0: stage edge data (vectorized) ----
        if (t < EB * 5) {                  // 120 float4 transfers
            int e = t / 5, q = t % 5;
            if (e < ecount)
                ((float4*)&es_sh[e][0])[q] =
                    __ldg(&((const float4*)&es_g[(size_t)(e0 + e) * ESZ])[q]);
        }
        if (t >= 160 && t < 160 + EB) {    // warp 5 handles metadata
            int l = t - 160;
            if (l < ecount) {
                int ge_ = e0 + l;
                src_sh[l] = eidx[2 * ge_];
                dst_sh[l] = eidx[2 * ge_ + 1];
                ev_sh[l][0] = ev_g[3 * ge_];
                ev_sh[l][1] = ev_g[3 * ge_ + 1];
                ev_sh[l][2] = ev_g[3 * ge_ + 2];
                float nrm = norms[ge_];
                fc_sh[l] = (nrm < CUTOFF) ? 0.5f * (cospif(nrm / CUTOFF) + 1.0f) : 0.0f;
            } else {
                src_sh[l] = 0; dst_sh[l] = 0;
                ev_sh[l][0] = ev_sh[l][1] = ev_sh[l][2] = 0.f;
                fc_sh[l] = 0.f;
            }
        }
        __syncthreads();

        // ---- phase 1: filter_output for two owned columns ----
        #pragma unroll 4
        for (int e = 0; e < EB; e++) {
            if (e >= ecount) break;
            int src = src_sh[e];
            float2 so = __ldg((const float2*)&g_so[(size_t)src * 384 + 2 * t]);
            float ax = bf2.x, ay = bf2.y;
            #pragma unroll
            for (int q = 0; q < 5; q++) {
                float4 e4 = *(const float4*)&es_sh[e][4 * q];
                ax = fmaf(e4.x, wf[4 * q + 0].x, ax);
                ay = fmaf(e4.x, wf[4 * q + 0].y, ay);
                ax = fmaf(e4.y, wf[4 * q + 1].x, ax);
                ay = fmaf(e4.y, wf[4 * q + 1].y, ay);
                ax = fmaf(e4.z, wf[4 * q + 2].x, ax);
                ay = fmaf(e4.z, wf[4 * q + 2].y, ay);
                ax = fmaf(e4.w, wf[4 * q + 3].x, ax);
                ay = fmaf(e4.w, wf[4 * q + 3].y, ay);
            }
            float fc = fc_sh[e];
            float2 fo;
            fo.x = ax * fc * so.x;
            fo.y = ay * fc * so.y;
            if (t < 128) {
                *(float2*)&fo_sh[e][2 * t] = fo;            // gn / ge segments
            } else {
                // ms segment: channels 2*(t-128), 2*(t-128)+1 -> direct reduction
                red_add_v2(&g_s[(size_t)dst_sh[e] * D + 2 * (t - 128)], fo);
            }
        }
        __syncthreads();

        // ---- phase 2: vector messages + scatter ----
        {
            int s = t & 31;
            int grp = t >> 5;   // 0..5
            #pragma unroll
            for (int ee = 0; ee < EB / 6; ee++) {
                int e = grp + 6 * ee;
                if (e >= ecount) continue;
                int dst = dst_sh[e];
                int src = src_sh[e];
                float4 gn = *(float4*)&fo_sh[e][4 * s];
                float4 ge = *(float4*)&fo_sh[e][D + 4 * s];
                #pragma unroll
                for (int c = 0; c < 3; c++) {
                    float evc = ev_sh[e][c];
                    float4 nv = __ldg((const float4*)&nsv[((size_t)src * 3 + c) * D + 4 * s]);
                    float4 mv;
                    mv.x = fmaf(nv.x, gn.x, ge.x * evc);
                    mv.y = fmaf(nv.y, gn.y, ge.y * evc);
                    mv.z = fmaf(nv.z, gn.z, ge.z * evc);
                    mv.w = fmaf(nv.w, gn.w, ge.w * evc);
                    red_add_v4(&g_v[((size_t)dst * 3 + c) * D + 4 * s], mv);
                }
            }
        }
        __syncthreads();
    }
}

// ---------------- per-node: Vv_sq, ip, concat ----------------
__global__ void vsq_ip_cat_kernel(int n) {
    int node = blockIdx.x;
    int i = threadIdx.x;  // 128
    float vsq = 0.f, ipv = 0.f;
    #pragma unroll
    for (int c = 0; c < 3; c++) {
        float u = g_Uv[((size_t)node * 3 + c) * D + i];
        float w = g_Vv[((size_t)node * 3 + c) * D + i];
        vsq += w * w;
        ipv += u * w;
    }
    g_cat[(size_t)node * 256 + i]       = g_s[(size_t)node * D + i];
    g_cat[(size_t)node * 256 + D + i]   = vsq;
    g_ip[(size_t)node * D + i]          = ipv;
}

// ---------------- final elementwise ----------------
__global__ void final_kernel(float* __restrict__ out, int n) {
    int node = blockIdx.x;
    int i = threadIdx.x;  // 128
    const float* a = &g_a[(size_t)node * 384];
    float a_ss = a[i];
    float a_sv = a[D + i];
    float a_vv = a[2 * D + i];
    out[(size_t)node * D + i] =
        g_s[(size_t)node * D + i] + a_ss + a_sv * g_ip[(size_t)node * D + i];
    float* vout = out + (size_t)n * D;
    #pragma unroll
    for (int c = 0; c < 3; c++) {
        size_t idx = ((size_t)node * 3 + c) * D + i;
        vout[idx] = g_v[idx] + a_vv * g_Uv[idx];
    }
}

// ---------------- launch ----------------
extern "C" void kernel_launch(void* const* d_in, const int* in_sizes, int n_in,
                              void* d_out, int out_size) {
    const float* ns  = (const float*)d_in[0];
    const float* nv  = (const float*)d_in[1];
    const float* es  = (const float*)d_in[2];
    const float* ev  = (const float*)d_in[3];
    const float* en  = (const float*)d_in[4];
    const int*   ei  = (const int*)  d_in[5];
    const float* Wf  = (const float*)d_in[6];
    const float* bf  = (const float*)d_in[7];
    const float* Wm1 = (const float*)d_in[8];
    const float* bm1 = (const float*)d_in[9];
    const float* Wm2 = (const float*)d_in[10];
    const float* bm2 = (const float*)d_in[11];
    const float* WU  = (const float*)d_in[12];
    const float* WV  = (const float*)d_in[13];
    const float* Wa1 = (const float*)d_in[14];
    const float* ba1 = (const float*)d_in[15];
    const float* Wa2 = (const float*)d_in[16];
    const float* ba2 = (const float*)d_in[17];

    int n = in_sizes[0] / D;
    int E = in_sizes[4];
    float* out = (float*)d_out;

    float *p_h1, *p_so, *p_v, *p_Uv, *p_Vv, *p_cat, *p_h2, *p_a;
    cudaGetSymbolAddress((void**)&p_h1,  g_h1);
    cudaGetSymbolAddress((void**)&p_so,  g_so);
    cudaGetSymbolAddress((void**)&p_v,   g_v);
    cudaGetSymbolAddress((void**)&p_Uv,  g_Uv);
    cudaGetSymbolAddress((void**)&p_Vv,  g_Vv);
    cudaGetSymbolAddress((void**)&p_cat, g_cat);
    cudaGetSymbolAddress((void**)&p_h2,  g_h2);
    cudaGetSymbolAddress((void**)&p_a,   g_a);

    // 1. init accumulators s = ns, v = nv
    init_copy_kernel<<<2048, 256>>>(ns, nv, n);

    // 2. H1 = silu(ns @ Wm1 + bm1)
    {
        dim3 grid((n + 127) / 128, 128 / 64);
        mma_gemm_kernel<true, true><<<grid, 256>>>(ns, Wm1, bm1, p_h1, n, 128, 128);
    }
    // 3. SO = H1 @ Wm2 + bm2
    {
        dim3 grid((n + 127) / 128, 384 / 64);
        mma_gemm_kernel<false, true><<<grid, 256>>>(p_h1, Wm2, bm2, p_so, n, 384, 128);
    }
    // 4. fused edge kernel
    {
        int nbatch = (E + EB - 1) / EB;
        int grid = nbatch < 2368 ? nbatch : 2368;
        edge_kernel<<<grid, 192>>>(es, ev, en, ei, Wf, bf, nv, E);
    }
    // 5/6. Uv = v @ WU, Vv = v @ WV
    {
        dim3 grid((3 * n + 127) / 128, 128 / 64);
        mma_gemm_kernel<false, false><<<grid, 256>>>(p_v, WU, nullptr, p_Uv, 3 * n, 128, 128);
        mma_gemm_kernel<false, false><<<grid, 256>>>(p_v, WV, nullptr, p_Vv, 3 * n, 128, 128);
    }
    // 7. Vv_sq, ip, cat
    vsq_ip_cat_kernel<<<n, 128>>>(n);

    // 8. H2 = silu(cat @ Wa1 + ba1)
    {
        dim3 grid((n + 127) / 128, 128 / 64);
        mma_gemm_kernel<true, true><<<grid, 256>>>(p_cat, Wa1, ba1, p_h2, n, 128, 256);
    }
    // 9. A = H2 @ Wa2 + ba2
    {
        dim3 grid((n + 127) / 128, 384 / 64);
        mma_gemm_kernel<false, true><<<grid, 256>>>(p_h2, Wa2, ba2, p_a, n, 384, 128);
    }
    // 10. final
    final_kernel<<<n, 128>>>(out, n);
}

// round 14
// speedup vs baseline: 1.8986x; 1.0192x over previous
#include <cuda_runtime.h>
#include <cuda_bf16.h>
#include <cstdio>
#include <cstdint>

#define D 128
#define ESZ 20
#define MAX_NODES 20000
#define MAX_EDGES 600000
#define CUTOFF 5.0f

// ---------------- scratch (static device bss; no allocations) ----------------
__device__ __align__(16) float g_h1 [MAX_NODES * D];
__device__ __align__(16) float g_so [MAX_NODES * 3 * D];
__device__ __align__(16) float g_s  [MAX_NODES * D];
__device__ __align__(16) float g_v  [MAX_NODES * 3 * D];
__device__ __align__(16) float g_Uv [MAX_NODES * 3 * D];
__device__ __align__(16) float g_Vv [MAX_NODES * 3 * D];
__device__ __align__(16) float g_cat[MAX_NODES * 2 * D];
__device__ __align__(16) float g_ip [MAX_NODES * D];
__device__ __align__(16) float g_h2 [MAX_NODES * D];
__device__ __align__(16) float g_a  [MAX_NODES * 3 * D];

// ---------------- helpers ----------------
__device__ __forceinline__ void red_add_v4(float* addr, float4 v) {
    asm volatile("red.global.add.v4.f32 [%0], {%1, %2, %3, %4};"
                 :: "l"(addr), "f"(v.x), "f"(v.y), "f"(v.z), "f"(v.w) : "memory");
}
__device__ __forceinline__ void red_add_v2(float* addr, float2 v) {
    asm volatile("red.global.add.v2.f32 [%0], {%1, %2};"
                 :: "l"(addr), "f"(v.x), "f"(v.y) : "memory");
}
__device__ __forceinline__ float silu_f(float x) {
    return x / (1.0f + __expf(-x));
}
__device__ __forceinline__ uint32_t f2tf32(float f) {
    uint32_t r;
    asm("cvt.rna.tf32.f32 %0, %1;" : "=r"(r) : "f"(f));
    return r;
}
__device__ __forceinline__ void mma_tf32(float c[4],
    uint32_t a0, uint32_t a1, uint32_t a2, uint32_t a3,
    uint32_t b0, uint32_t b1)
{
    asm volatile(
        "mma.sync.aligned.m16n8k8.row.col.f32.tf32.tf32.f32 "
        "{%0,%1,%2,%3}, {%4,%5,%6,%7}, {%8,%9}, {%0,%1,%2,%3};"
        : "+f"(c[0]), "+f"(c[1]), "+f"(c[2]), "+f"(c[3])
        : "r"(a0), "r"(a1), "r"(a2), "r"(a3), "r"(b0), "r"(b1));
}

// ---------------- init: copy node states into accumulators ----------------
__global__ void init_copy_kernel(const float* __restrict__ ns, const float* __restrict__ nv, int n) {
    int tid = blockIdx.x * blockDim.x + threadIdx.x;
    int stride = gridDim.x * blockDim.x;
    const float4* ns4 = (const float4*)ns;
    const float4* nv4 = (const float4*)nv;
    float4* s4 = (float4*)g_s;
    float4* v4 = (float4*)g_v;
    int cs = n * (D / 4);
    int cv = n * (3 * D / 4);
    for (int i = tid; i < cs; i += stride) s4[i] = ns4[i];
    for (int i = tid; i < cv; i += stride) v4[i] = nv4[i];
}

// ---------------- tf32 tensor-core GEMM: C = act(A[MxK] @ B[KxN] + bias) ----------------
template<bool SILU, bool HASBIAS>
__global__ __launch_bounds__(256) void mma_gemm_kernel(
    const float* __restrict__ A, const float* __restrict__ B,
    const float* __restrict__ bias, float* __restrict__ C,
    int M, int N, int K)
{
    const int BM = 128, BN = 64, BK = 16;
    __shared__ __align__(16) float As[BK][BM + 8];
    __shared__ __align__(16) float Bs[BK][BN + 8];
    int t = threadIdx.x;
    int lane = t & 31;
    int warp = t >> 5;
    int g = lane >> 2;
    int tig = lane & 3;
    int wm = warp & 3;
    int wn = warp >> 2;
    int m0 = blockIdx.x * BM;
    int n0 = blockIdx.y * BN;

    float c[2][4][4];
    #pragma unroll
    for (int mt = 0; mt < 2; mt++)
        #pragma unroll
        for (int nt = 0; nt < 4; nt++)
            #pragma unroll
            for (int i = 0; i < 4; i++) c[mt][nt][i] = 0.0f;

    for (int k0 = 0; k0 < K; k0 += BK) {
        #pragma unroll
        for (int it = 0; it < 2; it++) {
            int l = t + 256 * it;
            int row = l >> 2;
            int kc = (l & 3) * 4;
            float4 v = make_float4(0.f, 0.f, 0.f, 0.f);
            int gr = m0 + row;
            if (gr < M) v = *(const float4*)&A[(size_t)gr * K + k0 + kc];
            As[kc + 0][row] = v.x;
            As[kc + 1][row] = v.y;
            As[kc + 2][row] = v.z;
            As[kc + 3][row] = v.w;
        }
        {
            int row = t >> 4;
            int nc = (t & 15) * 4;
            *(float4*)&Bs[row][nc] = *(const float4*)&B[(size_t)(k0 + row) * N + n0 + nc];
        }
        __syncthreads();

        #pragma unroll
        for (int k8 = 0; k8 < BK; k8 += 8) {
            uint32_t a[2][4];
            #pragma unroll
            for (int mt = 0; mt < 2; mt++) {
                int mrow = wm * 32 + mt * 16;
                a[mt][0] = f2tf32(As[k8 + tig][mrow + g]);
                a[mt][1] = f2tf32(As[k8 + tig][mrow + g + 8]);
                a[mt][2] = f2tf32(As[k8 + tig + 4][mrow + g]);
                a[mt][3] = f2tf32(As[k8 + tig + 4][mrow + g + 8]);
            }
            uint32_t b[4][2];
            #pragma unroll
            for (int nt = 0; nt < 4; nt++) {
                int ncol = wn * 32 + nt * 8;
                b[nt][0] = f2tf32(Bs[k8 + tig][ncol + g]);
                b[nt][1] = f2tf32(Bs[k8 + tig + 4][ncol + g]);
            }
            #pragma unroll
            for (int mt = 0; mt < 2; mt++)
                #pragma unroll
                for (int nt = 0; nt < 4; nt++)
                    mma_tf32(c[mt][nt], a[mt][0], a[mt][1], a[mt][2], a[mt][3],
                             b[nt][0], b[nt][1]);
        }
        __syncthreads();
    }

    #pragma unroll
    for (int mt = 0; mt < 2; mt++) {
        #pragma unroll
        for (int nt = 0; nt < 4; nt++) {
            int row0 = m0 + wm * 32 + mt * 16 + g;
            int row1 = row0 + 8;
            int col = n0 + wn * 32 + nt * 8 + 2 * tig;
            float2 bv = make_float2(0.f, 0.f);
            if (HASBIAS) bv = *(const float2*)&bias[col];
            if (row0 < M) {
                float2 o;
                o.x = c[mt][nt][0] + bv.x;
                o.y = c[mt][nt][1] + bv.y;
                if (SILU) { o.x = silu_f(o.x); o.y = silu_f(o.y); }
                *(float2*)&C[(size_t)row0 * N + col] = o;
            }
            if (row1 < M) {
                float2 o;
                o.x = c[mt][nt][2] + bv.x;
                o.y = c[mt][nt][3] + bv.y;
                if (SILU) { o.x = silu_f(o.x); o.y = silu_f(o.y); }
                *(float2*)&C[(size_t)row1 * N + col] = o;
            }
        }
    }
}

// ---------------- fused edge kernel (v9: v8 + software pipeline) ----------------
// 192 threads, thread t owns filter cols {2t, 2t+1}. es+metadata double-buffered:
// next batch's LDGs issue into registers at iteration start (latency hidden under
// phase-1 FMAs), STS after. fo single-buffered. 2 barriers/batch (was 3).
#define EB 24
__global__ void __launch_bounds__(192, 4) edge_kernel(
    const float* __restrict__ es_g, const float* __restrict__ ev_g,
    const float* __restrict__ norms, const int* __restrict__ eidx,
    const float* __restrict__ Wf, const float* __restrict__ bf,
    const float* __restrict__ nsv, int E)
{
    __shared__ __align__(16) float es_sh[2][EB][ESZ];
    __shared__ __align__(16) float fo_sh[EB][2 * D];   // gn[128], ge[128]
    __shared__ int   src_sh[2][EB], dst_sh[2][EB];
    __shared__ float ev_sh[2][EB][3];
    __shared__ float fc_sh[2][EB];

    int t = threadIdx.x;

    float2 wf[ESZ];
    #pragma unroll
    for (int k = 0; k < ESZ; k++)
        wf[k] = *(const float2*)&Wf[k * 384 + 2 * t];
    float2 bf2 = *(const float2*)&bf[2 * t];

    int nbatch = (E + EB - 1) / EB;
    int stride = gridDim.x;
    int b = blockIdx.x;
    if (b >= nbatch) return;
    int cur = 0;

    // ---- prologue: stage first batch directly into buffer 0 ----
    {
        int e0 = b * EB;
        int ecount = min(EB, E - e0);
        if (t < EB * 5) {
            int e = t / 5, q = t % 5;
            float4 v = make_float4(0.f, 0.f, 0.f, 0.f);
            if (e < ecount)
                v = __ldg(&((const float4*)&es_g[(size_t)(e0 + e) * ESZ])[q]);
            ((float4*)&es_sh[0][e][0])[q] = v;
        }
        if (t >= 120 && t < 120 + EB) {
            int l = t - 120;
            if (l < ecount) {
                int ge_ = e0 + l;
                src_sh[0][l] = eidx[2 * ge_];
                dst_sh[0][l] = eidx[2 * ge_ + 1];
                ev_sh[0][l][0] = ev_g[3 * ge_];
                ev_sh[0][l][1] = ev_g[3 * ge_ + 1];
                ev_sh[0][l][2] = ev_g[3 * ge_ + 2];
                float nrm = norms[ge_];
                fc_sh[0][l] = (nrm < CUTOFF) ? 0.5f * (cospif(nrm / CUTOFF) + 1.0f) : 0.0f;
            } else {
                src_sh[0][l] = 0; dst_sh[0][l] = 0;
                ev_sh[0][l][0] = ev_sh[0][l][1] = ev_sh[0][l][2] = 0.f;
                fc_sh[0][l] = 0.f;
            }
        }
    }
    __syncthreads();

    for (; b < nbatch; b += stride, cur ^= 1) {
        int e0 = b * EB;
        int ecount = min(EB, E - e0);
        int bn = b + stride;
        bool have_next = (bn < nbatch);
        int ecn = have_next ? min(EB, E - bn * EB) : 0;

        // ---- issue next batch's loads into registers (latency hidden below) ----
        float4 r_es = make_float4(0.f, 0.f, 0.f, 0.f);
        int   r_src = 0, r_dst = 0;
        float r_ev0 = 0.f, r_ev1 = 0.f, r_ev2 = 0.f, r_fc = 0.f;
        if (have_next) {
            if (t < EB * 5) {
                int e = t / 5, q = t % 5;
                if (e < ecn)
                    r_es = __ldg(&((const float4*)&es_g[(size_t)(bn * EB + e) * ESZ])[q]);
            }
            if (t >= 120 && t < 120 + EB) {
                int l = t - 120;
                if (l < ecn) {
                    int ge_ = bn * EB + l;
                    r_src = __ldg(&eidx[2 * ge_]);
                    r_dst = __ldg(&eidx[2 * ge_ + 1]);
                    r_ev0 = __ldg(&ev_g[3 * ge_]);
                    r_ev1 = __ldg(&ev_g[3 * ge_ + 1]);
                    r_ev2 = __ldg(&ev_g[3 * ge_ + 2]);
                    float nrm = __ldg(&norms[ge_]);
                    r_fc = (nrm < CUTOFF) ? 0.5f * (cospif(nrm / CUTOFF) + 1.0f) : 0.0f;
                }
            }
        }

        // ---- phase 1: filter_output for two owned columns ----
        #pragma unroll 4
        for (int e = 0; e < EB; e++) {
            if (e >= ecount) break;
            int src = src_sh[cur][e];
            float2 so = __ldg((const float2*)&g_so[(size_t)src * 384 + 2 * t]);
            float ax = bf2.x, ay = bf2.y;
            #pragma unroll
            for (int q = 0; q < 5; q++) {
                float4 e4 = *(const float4*)&es_sh[cur][e][4 * q];
                ax = fmaf(e4.x, wf[4 * q + 0].x, ax);
                ay = fmaf(e4.x, wf[4 * q + 0].y, ay);
                ax = fmaf(e4.y, wf[4 * q + 1].x, ax);
                ay = fmaf(e4.y, wf[4 * q + 1].y, ay);
                ax = fmaf(e4.z, wf[4 * q + 2].x, ax);
                ay = fmaf(e4.z, wf[4 * q + 2].y, ay);
                ax = fmaf(e4.w, wf[4 * q + 3].x, ax);
                ay = fmaf(e4.w, wf[4 * q + 3].y, ay);
            }
            float fc = fc_sh[cur][e];
            float2 fo;
            fo.x = ax * fc * so.x;
            fo.y = ay * fc * so.y;
            if (t < 128) {
                *(float2*)&fo_sh[e][2 * t] = fo;
            } else {
                red_add_v2(&g_s[(size_t)dst_sh[cur][e] * D + 2 * (t - 128)], fo);
            }
        }

        // ---- commit next batch's staged data ----
        if (have_next) {
            int nxt = cur ^ 1;
            if (t < EB * 5) {
                int e = t / 5, q = t % 5;
                ((float4*)&es_sh[nxt][e][0])[q] = r_es;
            }
            if (t >= 120 && t < 120 + EB) {
                int l = t - 120;
                src_sh[nxt][l] = r_src;
                dst_sh[nxt][l] = r_dst;
                ev_sh[nxt][l][0] = r_ev0;
                ev_sh[nxt][l][1] = r_ev1;
                ev_sh[nxt][l][2] = r_ev2;
                fc_sh[nxt][l] = r_fc;
            }
        }
        __syncthreads();

        // ---- phase 2: vector messages + scatter ----
        {
            int s = t & 31;
            int grp = t >> 5;   // 0..5
            #pragma unroll
            for (int ee = 0; ee < EB / 6; ee++) {
                int e = grp + 6 * ee;
                if (e >= ecount) continue;
                int dst = dst_sh[cur][e];
                int src = src_sh[cur][e];
                float4 gn = *(float4*)&fo_sh[e][4 * s];
                float4 ge = *(float4*)&fo_sh[e][D + 4 * s];
                #pragma unroll
                for (int c = 0; c < 3; c++) {
                    float evc = ev_sh[cur][e][c];
                    float4 nv = __ldg((const float4*)&nsv[((size_t)src * 3 + c) * D + 4 * s]);
                    float4 mv;
                    mv.x = fmaf(nv.x, gn.x, ge.x * evc);
                    mv.y = fmaf(nv.y, gn.y, ge.y * evc);
                    mv.z = fmaf(nv.z, gn.z, ge.z * evc);
                    mv.w = fmaf(nv.w, gn.w, ge.w * evc);
                    red_add_v4(&g_v[((size_t)dst * 3 + c) * D + 4 * s], mv);
                }
            }
        }
        __syncthreads();
    }
}

// ---------------- per-node: Vv_sq, ip, concat ----------------
__global__ void vsq_ip_cat_kernel(int n) {
    int node = blockIdx.x;
    int i = threadIdx.x;  // 128
    float vsq = 0.f, ipv = 0.f;
    #pragma unroll
    for (int c = 0; c < 3; c++) {
        float u = g_Uv[((size_t)node * 3 + c) * D + i];
        float w = g_Vv[((size_t)node * 3 + c) * D + i];
        vsq += w * w;
        ipv += u * w;
    }
    g_cat[(size_t)node * 256 + i]       = g_s[(size_t)node * D + i];
    g_cat[(size_t)node * 256 + D + i]   = vsq;
    g_ip[(size_t)node * D + i]          = ipv;
}

// ---------------- final elementwise ----------------
__global__ void final_kernel(float* __restrict__ out, int n) {
    int node = blockIdx.x;
    int i = threadIdx.x;  // 128
    const float* a = &g_a[(size_t)node * 384];
    float a_ss = a[i];
    float a_sv = a[D + i];
    float a_vv = a[2 * D + i];
    out[(size_t)node * D + i] =
        g_s[(size_t)node * D + i] + a_ss + a_sv * g_ip[(size_t)node * D + i];
    float* vout = out + (size_t)n * D;
    #pragma unroll
    for (int c = 0; c < 3; c++) {
        size_t idx = ((size_t)node * 3 + c) * D + i;
        vout[idx] = g_v[idx] + a_vv * g_Uv[idx];
    }
}

// ---------------- launch ----------------
extern "C" void kernel_launch(void* const* d_in, const int* in_sizes, int n_in,
                              void* d_out, int out_size) {
    const float* ns  = (const float*)d_in[0];
    const float* nv  = (const float*)d_in[1];
    const float* es  = (const float*)d_in[2];
    const float* ev  = (const float*)d_in[3];
    const float* en  = (const float*)d_in[4];
    const int*   ei  = (const int*)  d_in[5];
    const float* Wf  = (const float*)d_in[6];
    const float* bf  = (const float*)d_in[7];
    const float* Wm1 = (const float*)d_in[8];
    const float* bm1 = (const float*)d_in[9];
    const float* Wm2 = (const float*)d_in[10];
    const float* bm2 = (const float*)d_in[11];
    const float* WU  = (const float*)d_in[12];
    const float* WV  = (const float*)d_in[13];
    const float* Wa1 = (const float*)d_in[14];
    const float* ba1 = (const float*)d_in[15];
    const float* Wa2 = (const float*)d_in[16];
    const float* ba2 = (const float*)d_in[17];

    int n = in_sizes[0] / D;
    int E = in_sizes[4];
    float* out = (float*)d_out;

    float *p_h1, *p_so, *p_v, *p_Uv, *p_Vv, *p_cat, *p_h2, *p_a;
    cudaGetSymbolAddress((void**)&p_h1,  g_h1);
    cudaGetSymbolAddress((void**)&p_so,  g_so);
    cudaGetSymbolAddress((void**)&p_v,   g_v);
    cudaGetSymbolAddress((void**)&p_Uv,  g_Uv);
    cudaGetSymbolAddress((void**)&p_Vv,  g_Vv);
    cudaGetSymbolAddress((void**)&p_cat, g_cat);
    cudaGetSymbolAddress((void**)&p_h2,  g_h2);
    cudaGetSymbolAddress((void**)&p_a,   g_a);

    // 1. init accumulators s = ns, v = nv
    init_copy_kernel<<<2048, 256>>>(ns, nv, n);

    // 2. H1 = silu(ns @ Wm1 + bm1)
    {
        dim3 grid((n + 127) / 128, 128 / 64);
        mma_gemm_kernel<true, true><<<grid, 256>>>(ns, Wm1, bm1, p_h1, n, 128, 128);
    }
    // 3. SO = H1 @ Wm2 + bm2
    {
        dim3 grid((n + 127) / 128, 384 / 64);
        mma_gemm_kernel<false, true><<<grid, 256>>>(p_h1, Wm2, bm2, p_so, n, 384, 128);
    }
    // 4. fused edge kernel (pipelined)
    {
        int nbatch = (E + EB - 1) / EB;
        int grid = nbatch < 2368 ? nbatch : 2368;
        edge_kernel<<<grid, 192>>>(es, ev, en, ei, Wf, bf, nv, E);
    }
    // 5/6. Uv = v @ WU, Vv = v @ WV
    {
        dim3 grid((3 * n + 127) / 128, 128 / 64);
        mma_gemm_kernel<false, false><<<grid, 256>>>(p_v, WU, nullptr, p_Uv, 3 * n, 128, 128);
        mma_gemm_kernel<false, false><<<grid, 256>>>(p_v, WV, nullptr, p_Vv, 3 * n, 128, 128);
    }
    // 7. Vv_sq, ip, cat
    vsq_ip_cat_kernel<<<n, 128>>>(n);

    // 8. H2 = silu(cat @ Wa1 + ba1)
    {
        dim3 grid((n + 127) / 128, 128 / 64);
        mma_gemm_kernel<true, true><<<grid, 256>>>(p_cat, Wa1, ba1, p_h2, n, 128, 256);
    }
    // 9. A = H2 @ Wa2 + ba2
    {
        dim3 grid((n + 127) / 128, 384 / 64);
        mma_gemm_kernel<false, true><<<grid, 256>>>(p_h2, Wa2, ba2, p_a, n, 384, 128);
    }
    // 10. final
    final_kernel<<<n, 128>>>(out, n);
}